// round 9
// baseline (speedup 1.0000x reference)
#include <cuda_runtime.h>
#include <cuda_fp16.h>
#include <cstdint>

#define BS   4
#define SEQ  4096
#define FDIM 512
#define DDIM 64
#define M_TOTAL (BS*SEQ)
#define NSPLIT 4
#define KT_PER (SEQ / 64 / NSPLIT)   // 16

// fp16 projected tensors: Q (scaled 0.125*log2e) [b,s,d], K [b,s,d], V^T [b,d,s]
__device__ __half g_Qh[(size_t)M_TOTAL * DDIM];
__device__ __half g_Kh[(size_t)M_TOTAL * DDIM];
__device__ __half g_VTh[(size_t)BS * DDIM * SEQ];
// fp16 transposed weights: rows n (0-63 Q, 64-127 K, 128-191 V), cols k (512)
__device__ __half g_WT[192 * FDIM];
// Split-K partials
__device__ float g_Opart[NSPLIT * (size_t)M_TOTAL * DDIM];
__device__ float g_Lpart[NSPLIT * M_TOTAL];

// ---------------------------------------------------------------------------
// helpers
// ---------------------------------------------------------------------------
__device__ __forceinline__ float ex2(float x) {
    float y;
    asm("ex2.approx.f32 %0, %1;" : "=f"(y) : "f"(x));
    return y;
}
__device__ __forceinline__ uint32_t hpack(float a, float b) {
    __half2 h = __floats2half2_rn(a, b);
    return *(uint32_t*)&h;
}
__device__ __forceinline__ void mma16(float* d,
                                      uint32_t a0, uint32_t a1, uint32_t a2, uint32_t a3,
                                      uint32_t b0, uint32_t b1) {
    asm volatile("mma.sync.aligned.m16n8k16.row.col.f32.f16.f16.f32 "
        "{%0,%1,%2,%3}, {%4,%5,%6,%7}, {%8,%9}, {%0,%1,%2,%3};"
        : "+f"(d[0]), "+f"(d[1]), "+f"(d[2]), "+f"(d[3])
        : "r"(a0), "r"(a1), "r"(a2), "r"(a3), "r"(b0), "r"(b1));
}
__device__ __forceinline__ uint32_t LDSH2(const __half* p) {
    return *(const uint32_t*)p;
}
__device__ __forceinline__ void cp16(uint32_t s, const void* g) {
    asm volatile("cp.async.ca.shared.global [%0], [%1], 16;" :: "r"(s), "l"(g) : "memory");
}
#define CP_COMMIT() asm volatile("cp.async.commit_group;" ::: "memory")
#define CP_WAIT0()  asm volatile("cp.async.wait_group 0;" ::: "memory")
#define CP_WAIT1()  asm volatile("cp.async.wait_group 1;" ::: "memory")

// ---------------------------------------------------------------------------
// prep_w: W{q,k,v} fp32 [512,64] -> g_WT fp16 [192][512] (transposed),
// Q-scale 0.125*log2e folded into rows 0-63.
// ---------------------------------------------------------------------------
__global__ __launch_bounds__(256) void prep_w(
    const float* __restrict__ Wq,
    const float* __restrict__ Wk,
    const float* __restrict__ Wv)
{
    const int idx = blockIdx.x * 256 + threadIdx.x;
    const int n = idx >> 9;
    const int k = idx & 511;
    const float* W = (n < 64) ? Wq : ((n < 128) ? Wk : Wv);
    const float s = (n < 64) ? 0.125f * 1.44269504f : 1.0f;
    g_WT[idx] = __float2half_rn(W[(size_t)k * DDIM + (n & 63)] * s);
}

// ---------------------------------------------------------------------------
// Fused QKV projection, plain fp16 tensor GEMM. (unchanged from R8)
// ---------------------------------------------------------------------------
#define QXS 0
#define QWS 9216
#define SMEM_QKV ((9216 + 27648) * 2)

__global__ __launch_bounds__(256, 2) void qkv_tc(const float* __restrict__ x)
{
    extern __shared__ __half smh[];
    const uint32_t smem_u32 = (uint32_t)__cvta_generic_to_shared(smh);

    const int rbase = blockIdx.x * 64;
    const int tid  = threadIdx.x;
    const int lane = tid & 31;
    const int wid  = tid >> 5;
    const int g  = lane >> 2;
    const int tg = lane & 3;
    const int rp   = wid & 1;
    const int colq = wid >> 1;

    const int xrow = tid >> 2;
    const int xc16 = (tid & 3) * 16;

    float acc[2][6][4];
    #pragma unroll
    for (int mt = 0; mt < 2; mt++)
        #pragma unroll
        for (int nt = 0; nt < 6; nt++)
            #pragma unroll
            for (int e = 0; e < 4; e++) acc[mt][nt][e] = 0.f;

    #pragma unroll
    for (int i = 0; i < 6; i++) {
        int idx = tid + i * 256;
        int row = idx >> 3, c = idx & 7;
        cp16(smem_u32 + QWS * 2 + row * 144 + c * 16,
             (const char*)g_WT + (size_t)row * FDIM * 2 + c * 16);
    }
    CP_COMMIT();

    float4 xr[4];
    #pragma unroll
    for (int i = 0; i < 4; i++)
        xr[i] = *(const float4*)&x[(size_t)(rbase + xrow) * FDIM + xc16 + i * 4];

    #pragma unroll 1
    for (int kc = 0; kc < 8; kc++) {
        const int buf = kc & 1;
        __half* Xs = smh + QXS + buf * 4608;
        const __half* Ws = smh + QWS + buf * 13824;

        {
            uint4 u0, u1;
            u0.x = hpack(xr[0].x, xr[0].y); u0.y = hpack(xr[0].z, xr[0].w);
            u0.z = hpack(xr[1].x, xr[1].y); u0.w = hpack(xr[1].z, xr[1].w);
            u1.x = hpack(xr[2].x, xr[2].y); u1.y = hpack(xr[2].z, xr[2].w);
            u1.z = hpack(xr[3].x, xr[3].y); u1.w = hpack(xr[3].z, xr[3].w);
            *(uint4*)&Xs[xrow * 72 + xc16]     = u0;
            *(uint4*)&Xs[xrow * 72 + xc16 + 8] = u1;
        }
        if (kc < 7) {
            #pragma unroll
            for (int i = 0; i < 4; i++)
                xr[i] = *(const float4*)&x[(size_t)(rbase + xrow) * FDIM
                                           + (kc + 1) * 64 + xc16 + i * 4];
        }

        CP_WAIT0();
        __syncthreads();

        if (kc < 7) {
            const int nb = (kc + 1) & 1;
            #pragma unroll
            for (int i = 0; i < 6; i++) {
                int idx = tid + i * 256;
                int row = idx >> 3, c = idx & 7;
                cp16(smem_u32 + QWS * 2 + nb * 27648 + row * 144 + c * 16,
                     (const char*)g_WT + (size_t)row * FDIM * 2 + (kc + 1) * 128 + c * 16);
            }
            CP_COMMIT();
        }

        #pragma unroll
        for (int ks = 0; ks < 4; ks++) {
            const int kcol = ks * 16 + 2 * tg;
            uint32_t a[2][4];
            #pragma unroll
            for (int mt = 0; mt < 2; mt++) {
                const int r0 = rp * 32 + mt * 16;
                a[mt][0] = LDSH2(&Xs[(r0 + g    ) * 72 + kcol]);
                a[mt][1] = LDSH2(&Xs[(r0 + g + 8) * 72 + kcol]);
                a[mt][2] = LDSH2(&Xs[(r0 + g    ) * 72 + kcol + 8]);
                a[mt][3] = LDSH2(&Xs[(r0 + g + 8) * 72 + kcol + 8]);
            }
            #pragma unroll
            for (int nt = 0; nt < 6; nt++) {
                const int n = colq * 48 + nt * 8 + g;
                uint32_t b0 = LDSH2(&Ws[n * 72 + kcol]);
                uint32_t b1 = LDSH2(&Ws[n * 72 + kcol + 8]);
                mma16(acc[0][nt], a[0][0], a[0][1], a[0][2], a[0][3], b0, b1);
                mma16(acc[1][nt], a[1][0], a[1][1], a[1][2], a[1][3], b0, b1);
            }
        }
    }
    __syncthreads();

    __half* T = smh;
    #pragma unroll
    for (int mt = 0; mt < 2; mt++) {
        #pragma unroll
        for (int nt = 0; nt < 6; nt++) {
            const int n = colq * 48 + nt * 8 + 2 * tg;
            const int r0 = rbase + rp * 32 + mt * 16;
            if (n < 64) {
                *(uint32_t*)&g_Qh[(size_t)(r0 + g    ) * DDIM + n] =
                    hpack(acc[mt][nt][0], acc[mt][nt][1]);
                *(uint32_t*)&g_Qh[(size_t)(r0 + g + 8) * DDIM + n] =
                    hpack(acc[mt][nt][2], acc[mt][nt][3]);
            } else if (n < 128) {
                *(uint32_t*)&g_Kh[(size_t)(r0 + g    ) * DDIM + n - 64] =
                    hpack(acc[mt][nt][0], acc[mt][nt][1]);
                *(uint32_t*)&g_Kh[(size_t)(r0 + g + 8) * DDIM + n - 64] =
                    hpack(acc[mt][nt][2], acc[mt][nt][3]);
            } else {
                const int d = n - 128;
                const int s0 = rp * 32 + mt * 16;
                T[(d    ) * 72 + s0 + g    ] = __float2half_rn(acc[mt][nt][0]);
                T[(d + 1) * 72 + s0 + g    ] = __float2half_rn(acc[mt][nt][1]);
                T[(d    ) * 72 + s0 + g + 8] = __float2half_rn(acc[mt][nt][2]);
                T[(d + 1) * 72 + s0 + g + 8] = __float2half_rn(acc[mt][nt][3]);
            }
        }
    }
    __syncthreads();
    {
        const int b = rbase >> 12;
        const int sbase = rbase & 4095;
        #pragma unroll
        for (int i = 0; i < 2; i++) {
            int idx = tid + i * 256;
            int d = idx >> 3, c8 = idx & 7;
            uint4 v = *(const uint4*)&T[d * 72 + c8 * 8];
            *(uint4*)&g_VTh[((size_t)b * DDIM + d) * SEQ + sbase + c8 * 8] = v;
        }
    }
}

// ---------------------------------------------------------------------------
// fp16 mma flash attention: 4 warps x 32 query rows, split-K=4, 3 CTAs/SM.
// grid (SEQ/128, B, NSPLIT), block 128.
// SMEM bytes: K[2][9216] V[2][9216] P[4][32*144] Q[128*144]  = 73728 B
// B-fragments (K and V) are shared across the warp's two M-tiles.
// ---------------------------------------------------------------------------
#define KB_OFF 0
#define VB_OFF 18432
#define PB_OFF 36864
#define QS_OFF 55296
#define SMEM_ATTN 73728

__global__ __launch_bounds__(128, 3) void attn_mma()
{
    extern __shared__ __half smah[];
    char* smb = (char*)smah;
    const uint32_t smem_u32 = (uint32_t)__cvta_generic_to_shared(smb);

    const int tid  = threadIdx.x;
    const int lane = tid & 31;
    const int wid  = tid >> 5;          // 0..3
    const int g  = lane >> 2;
    const int tg = lane & 3;
    const int b     = blockIdx.y;
    const int split = blockIdx.z;
    const int qbase = blockIdx.x * 128;
    const int qrow0 = wid * 32;

    __half* Qs = (__half*)(smb + QS_OFF);                      // [128][72]
    __half* Ps = (__half*)(smb + PB_OFF) + wid * (32 * 72);    // [32][72] per warp

    // ---- Q tile into smem: thread tid copies row tid (warp-private rows) ----
    {
        const uint4* src = (const uint4*)(g_Qh + ((size_t)b * SEQ + qbase + tid) * DDIM);
        uint4* dst = (uint4*)(Qs + tid * 72);
        #pragma unroll
        for (int c = 0; c < 8; c++) dst[c] = src[c];
    }

    float oacc[2][8][4];
    float lrow[4] = {0.f, 0.f, 0.f, 0.f};
    #pragma unroll
    for (int mt = 0; mt < 2; mt++)
        #pragma unroll
        for (int nt = 0; nt < 8; nt++)
            #pragma unroll
            for (int e = 0; e < 4; e++) oacc[mt][nt][e] = 0.f;

    const __half* Kb = g_Kh + ((size_t)b * SEQ + (size_t)split * (SEQ / NSPLIT)) * DDIM;
    const __half* Vb = g_VTh + (size_t)b * DDIM * SEQ + (size_t)split * (SEQ / NSPLIT);

    // fill coords: 64 rows x 8 chunks of 16B per tensor; 128 threads x 4 chunks
    const int frow = tid >> 1;
    const int fc   = (tid & 1) * 4;

    // prologue: tile 0 into buffer 0
    #pragma unroll
    for (int c = 0; c < 4; c++) {
        cp16(smem_u32 + KB_OFF + frow * 144 + (fc + c) * 16,
             (const char*)Kb + frow * 128 + (fc + c) * 16);
        cp16(smem_u32 + VB_OFF + frow * 144 + (fc + c) * 16,
             (const char*)Vb + (size_t)frow * (SEQ * 2) + (fc + c) * 16);
    }
    CP_COMMIT();

    #pragma unroll 1
    for (int kt = 0; kt < KT_PER; kt++) {
        // fill next tile (buffer released by trailing barrier of iter kt-1)
        {
            int nk = (kt + 1 < KT_PER) ? kt + 1 : kt;
            int nb = (kt + 1) & 1;
            const char* Kg = (const char*)(Kb + (size_t)nk * 64 * DDIM);
            const char* Vg = (const char*)(Vb + (size_t)nk * 64);
            #pragma unroll
            for (int c = 0; c < 4; c++) {
                cp16(smem_u32 + KB_OFF + nb * 9216 + frow * 144 + (fc + c) * 16,
                     Kg + frow * 128 + (fc + c) * 16);
                cp16(smem_u32 + VB_OFF + nb * 9216 + frow * 144 + (fc + c) * 16,
                     Vg + (size_t)frow * (SEQ * 2) + (fc + c) * 16);
            }
            CP_COMMIT();
        }
        CP_WAIT1();
        __syncthreads();

        const __half* Ks = (const __half*)(smb + KB_OFF) + (kt & 1) * 4608;
        const __half* Vs = (const __half*)(smb + VB_OFF) + (kt & 1) * 4608;

        // ---- S = Q @ K^T : 2 mtiles share every K B-fragment ----
        float sacc[2][8][4];
        #pragma unroll
        for (int mt = 0; mt < 2; mt++)
            #pragma unroll
            for (int nt = 0; nt < 8; nt++)
                #pragma unroll
                for (int e = 0; e < 4; e++) sacc[mt][nt][e] = 0.f;

        #pragma unroll
        for (int ks = 0; ks < 4; ks++) {
            const int kcol = ks * 16 + 2 * tg;
            uint32_t a[2][4];
            #pragma unroll
            for (int mt = 0; mt < 2; mt++) {
                const int r0 = qrow0 + mt * 16;
                a[mt][0] = LDSH2(&Qs[(r0 + g    ) * 72 + kcol]);
                a[mt][1] = LDSH2(&Qs[(r0 + g + 8) * 72 + kcol]);
                a[mt][2] = LDSH2(&Qs[(r0 + g    ) * 72 + kcol + 8]);
                a[mt][3] = LDSH2(&Qs[(r0 + g + 8) * 72 + kcol + 8]);
            }
            #pragma unroll
            for (int nt = 0; nt < 8; nt++) {
                uint32_t b0 = LDSH2(&Ks[(nt * 8 + g) * 72 + kcol]);
                uint32_t b1 = LDSH2(&Ks[(nt * 8 + g) * 72 + kcol + 8]);
                mma16(sacc[0][nt], a[0][0], a[0][1], a[0][2], a[0][3], b0, b1);
                mma16(sacc[1][nt], a[1][0], a[1][1], a[1][2], a[1][3], b0, b1);
            }
        }

        // ---- P = 2^S, row sums, store P fp16 (per-warp region) ----
        #pragma unroll
        for (int mt = 0; mt < 2; mt++) {
            #pragma unroll
            for (int nt = 0; nt < 8; nt++) {
                float e0 = ex2(sacc[mt][nt][0]);
                float e1 = ex2(sacc[mt][nt][1]);
                float e2 = ex2(sacc[mt][nt][2]);
                float e3 = ex2(sacc[mt][nt][3]);
                lrow[mt * 2 + 0] += e0 + e1;
                lrow[mt * 2 + 1] += e2 + e3;
                *(uint32_t*)&Ps[(mt * 16 + g    ) * 72 + nt * 8 + 2 * tg] = hpack(e0, e1);
                *(uint32_t*)&Ps[(mt * 16 + 8 + g) * 72 + nt * 8 + 2 * tg] = hpack(e2, e3);
            }
        }
        __syncwarp();

        // ---- O += P @ V : 2 mtiles share every V B-fragment ----
        #pragma unroll
        for (int ks = 0; ks < 4; ks++) {
            const int kcol = ks * 16 + 2 * tg;
            uint32_t p[2][4];
            #pragma unroll
            for (int mt = 0; mt < 2; mt++) {
                const int r0 = mt * 16;
                p[mt][0] = LDSH2(&Ps[(r0 + g    ) * 72 + kcol]);
                p[mt][1] = LDSH2(&Ps[(r0 + g + 8) * 72 + kcol]);
                p[mt][2] = LDSH2(&Ps[(r0 + g    ) * 72 + kcol + 8]);
                p[mt][3] = LDSH2(&Ps[(r0 + g + 8) * 72 + kcol + 8]);
            }
            #pragma unroll
            for (int nt = 0; nt < 8; nt++) {
                uint32_t b0 = LDSH2(&Vs[(nt * 8 + g) * 72 + kcol]);
                uint32_t b1 = LDSH2(&Vs[(nt * 8 + g) * 72 + kcol + 8]);
                mma16(oacc[0][nt], p[0][0], p[0][1], p[0][2], p[0][3], b0, b1);
                mma16(oacc[1][nt], p[1][0], p[1][1], p[1][2], p[1][3], b0, b1);
            }
        }
        __syncthreads();   // release buffer kt&1 before iter kt+1 overwrites it
    }

    // ---- quad-reduce row sums ----
    #pragma unroll
    for (int i = 0; i < 4; i++) {
        lrow[i] += __shfl_xor_sync(0xffffffffu, lrow[i], 1);
        lrow[i] += __shfl_xor_sync(0xffffffffu, lrow[i], 2);
    }

    // ---- store unnormalized partials ----
    const size_t rbase = (size_t)split * M_TOTAL + (size_t)b * SEQ + qbase + qrow0;
    #pragma unroll
    for (int mt = 0; mt < 2; mt++) {
        #pragma unroll
        for (int nt = 0; nt < 8; nt++) {
            float2 o0, o1;
            o0.x = oacc[mt][nt][0]; o0.y = oacc[mt][nt][1];
            o1.x = oacc[mt][nt][2]; o1.y = oacc[mt][nt][3];
            *(float2*)&g_Opart[(rbase + mt * 16 + g    ) * DDIM + nt * 8 + 2 * tg] = o0;
            *(float2*)&g_Opart[(rbase + mt * 16 + 8 + g) * DDIM + nt * 8 + 2 * tg] = o1;
        }
    }
    if (tg == 0) {
        g_Lpart[rbase + g]          = lrow[0];
        g_Lpart[rbase + g + 8]      = lrow[1];
        g_Lpart[rbase + 16 + g]     = lrow[2];
        g_Lpart[rbase + 16 + g + 8] = lrow[3];
    }
}

// ---------------------------------------------------------------------------
// Combine: out = (O0+O1+O2+O3) / (l0+l1+l2+l3)
// ---------------------------------------------------------------------------
__global__ __launch_bounds__(256) void combine(float* __restrict__ out)
{
    const int i = blockIdx.x * 256 + threadIdx.x;
    const int row = i >> 4;
    float l = 0.f;
    #pragma unroll
    for (int s = 0; s < NSPLIT; s++) l += g_Lpart[s * M_TOTAL + row];
    const float inv = 1.0f / l;

    float4 r = make_float4(0.f, 0.f, 0.f, 0.f);
    #pragma unroll
    for (int s = 0; s < NSPLIT; s++) {
        const float4 a = *(const float4*)&g_Opart[(size_t)s * M_TOTAL * DDIM + (size_t)i * 4];
        r.x += a.x; r.y += a.y; r.z += a.z; r.w += a.w;
    }
    r.x *= inv; r.y *= inv; r.z *= inv; r.w *= inv;
    *(float4*)&out[(size_t)i * 4] = r;
}

// ---------------------------------------------------------------------------
extern "C" void kernel_launch(void* const* d_in, const int* in_sizes, int n_in,
                              void* d_out, int out_size)
{
    const float* x  = (const float*)d_in[0];
    const float* Wq = (const float*)d_in[1];
    const float* Wk = (const float*)d_in[2];
    const float* Wv = (const float*)d_in[3];
    float* out = (float*)d_out;

    cudaFuncSetAttribute(qkv_tc,   cudaFuncAttributeMaxDynamicSharedMemorySize, SMEM_QKV);
    cudaFuncSetAttribute(attn_mma, cudaFuncAttributeMaxDynamicSharedMemorySize, SMEM_ATTN);

    prep_w<<<192 * FDIM / 256, 256>>>(Wq, Wk, Wv);
    qkv_tc<<<M_TOTAL / 64, 256, SMEM_QKV>>>(x);
    attn_mma<<<dim3(SEQ / 128, BS, NSPLIT), 128, SMEM_ATTN>>>();
    combine<<<(M_TOTAL * DDIM / 4) / 256, 256>>>(out);
}

// round 10
// speedup vs baseline: 1.1325x; 1.1325x over previous
#include <cuda_runtime.h>
#include <cuda_fp16.h>
#include <cstdint>

#define BS   4
#define SEQ  4096
#define FDIM 512
#define DDIM 64
#define M_TOTAL (BS*SEQ)
#define NSPLIT 2
#define KT_PER (SEQ / 64 / NSPLIT)   // 32

// fp16 projected tensors: Q (scaled 0.125*log2e) [b,s,d], K [b,s,d], V^T [b,d,s]
__device__ __half g_Qh[(size_t)M_TOTAL * DDIM];
__device__ __half g_Kh[(size_t)M_TOTAL * DDIM];
__device__ __half g_VTh[(size_t)BS * DDIM * SEQ];
// fp16 transposed weights: rows n (0-63 Q, 64-127 K, 128-191 V), cols k (512)
__device__ __half g_WT[192 * FDIM];
// Split-K partials
__device__ float g_Opart[NSPLIT * (size_t)M_TOTAL * DDIM];
__device__ float g_Lpart[NSPLIT * M_TOTAL];

// ---------------------------------------------------------------------------
// helpers
// ---------------------------------------------------------------------------
__device__ __forceinline__ float ex2(float x) {
    float y;
    asm("ex2.approx.f32 %0, %1;" : "=f"(y) : "f"(x));
    return y;
}
__device__ __forceinline__ uint32_t hpack(float a, float b) {
    __half2 h = __floats2half2_rn(a, b);
    return *(uint32_t*)&h;
}
__device__ __forceinline__ void mma16(float* d,
                                      uint32_t a0, uint32_t a1, uint32_t a2, uint32_t a3,
                                      uint32_t b0, uint32_t b1) {
    asm volatile("mma.sync.aligned.m16n8k16.row.col.f32.f16.f16.f32 "
        "{%0,%1,%2,%3}, {%4,%5,%6,%7}, {%8,%9}, {%0,%1,%2,%3};"
        : "+f"(d[0]), "+f"(d[1]), "+f"(d[2]), "+f"(d[3])
        : "r"(a0), "r"(a1), "r"(a2), "r"(a3), "r"(b0), "r"(b1));
}
__device__ __forceinline__ uint32_t LDSH2(const __half* p) {
    return *(const uint32_t*)p;
}
__device__ __forceinline__ void cp16(uint32_t s, const void* g) {
    asm volatile("cp.async.ca.shared.global [%0], [%1], 16;" :: "r"(s), "l"(g) : "memory");
}
#define CP_COMMIT() asm volatile("cp.async.commit_group;" ::: "memory")
#define CP_WAIT0()  asm volatile("cp.async.wait_group 0;" ::: "memory")
#define CP_WAIT1()  asm volatile("cp.async.wait_group 1;" ::: "memory")

// ---------------------------------------------------------------------------
// prep_w: W{q,k,v} fp32 [512,64] -> g_WT fp16 [192][512] (transposed),
// Q-scale 0.125*log2e folded into rows 0-63.
// ---------------------------------------------------------------------------
__global__ __launch_bounds__(256) void prep_w(
    const float* __restrict__ Wq,
    const float* __restrict__ Wk,
    const float* __restrict__ Wv)
{
    const int idx = blockIdx.x * 256 + threadIdx.x;
    const int n = idx >> 9;
    const int k = idx & 511;
    const float* W = (n < 64) ? Wq : ((n < 128) ? Wk : Wv);
    const float s = (n < 64) ? 0.125f * 1.44269504f : 1.0f;
    g_WT[idx] = __float2half_rn(W[(size_t)k * DDIM + (n & 63)] * s);
}

// ---------------------------------------------------------------------------
// Fused QKV projection, plain fp16 tensor GEMM. (unchanged from R8)
// ---------------------------------------------------------------------------
#define QXS 0
#define QWS 9216
#define SMEM_QKV ((9216 + 27648) * 2)

__global__ __launch_bounds__(256, 2) void qkv_tc(const float* __restrict__ x)
{
    extern __shared__ __half smh[];
    const uint32_t smem_u32 = (uint32_t)__cvta_generic_to_shared(smh);

    const int rbase = blockIdx.x * 64;
    const int tid  = threadIdx.x;
    const int lane = tid & 31;
    const int wid  = tid >> 5;
    const int g  = lane >> 2;
    const int tg = lane & 3;
    const int rp   = wid & 1;
    const int colq = wid >> 1;

    const int xrow = tid >> 2;
    const int xc16 = (tid & 3) * 16;

    float acc[2][6][4];
    #pragma unroll
    for (int mt = 0; mt < 2; mt++)
        #pragma unroll
        for (int nt = 0; nt < 6; nt++)
            #pragma unroll
            for (int e = 0; e < 4; e++) acc[mt][nt][e] = 0.f;

    #pragma unroll
    for (int i = 0; i < 6; i++) {
        int idx = tid + i * 256;
        int row = idx >> 3, c = idx & 7;
        cp16(smem_u32 + QWS * 2 + row * 144 + c * 16,
             (const char*)g_WT + (size_t)row * FDIM * 2 + c * 16);
    }
    CP_COMMIT();

    float4 xr[4];
    #pragma unroll
    for (int i = 0; i < 4; i++)
        xr[i] = *(const float4*)&x[(size_t)(rbase + xrow) * FDIM + xc16 + i * 4];

    #pragma unroll 1
    for (int kc = 0; kc < 8; kc++) {
        const int buf = kc & 1;
        __half* Xs = smh + QXS + buf * 4608;
        const __half* Ws = smh + QWS + buf * 13824;

        {
            uint4 u0, u1;
            u0.x = hpack(xr[0].x, xr[0].y); u0.y = hpack(xr[0].z, xr[0].w);
            u0.z = hpack(xr[1].x, xr[1].y); u0.w = hpack(xr[1].z, xr[1].w);
            u1.x = hpack(xr[2].x, xr[2].y); u1.y = hpack(xr[2].z, xr[2].w);
            u1.z = hpack(xr[3].x, xr[3].y); u1.w = hpack(xr[3].z, xr[3].w);
            *(uint4*)&Xs[xrow * 72 + xc16]     = u0;
            *(uint4*)&Xs[xrow * 72 + xc16 + 8] = u1;
        }
        if (kc < 7) {
            #pragma unroll
            for (int i = 0; i < 4; i++)
                xr[i] = *(const float4*)&x[(size_t)(rbase + xrow) * FDIM
                                           + (kc + 1) * 64 + xc16 + i * 4];
        }

        CP_WAIT0();
        __syncthreads();

        if (kc < 7) {
            const int nb = (kc + 1) & 1;
            #pragma unroll
            for (int i = 0; i < 6; i++) {
                int idx = tid + i * 256;
                int row = idx >> 3, c = idx & 7;
                cp16(smem_u32 + QWS * 2 + nb * 27648 + row * 144 + c * 16,
                     (const char*)g_WT + (size_t)row * FDIM * 2 + (kc + 1) * 128 + c * 16);
            }
            CP_COMMIT();
        }

        #pragma unroll
        for (int ks = 0; ks < 4; ks++) {
            const int kcol = ks * 16 + 2 * tg;
            uint32_t a[2][4];
            #pragma unroll
            for (int mt = 0; mt < 2; mt++) {
                const int r0 = rp * 32 + mt * 16;
                a[mt][0] = LDSH2(&Xs[(r0 + g    ) * 72 + kcol]);
                a[mt][1] = LDSH2(&Xs[(r0 + g + 8) * 72 + kcol]);
                a[mt][2] = LDSH2(&Xs[(r0 + g    ) * 72 + kcol + 8]);
                a[mt][3] = LDSH2(&Xs[(r0 + g + 8) * 72 + kcol + 8]);
            }
            #pragma unroll
            for (int nt = 0; nt < 6; nt++) {
                const int n = colq * 48 + nt * 8 + g;
                uint32_t b0 = LDSH2(&Ws[n * 72 + kcol]);
                uint32_t b1 = LDSH2(&Ws[n * 72 + kcol + 8]);
                mma16(acc[0][nt], a[0][0], a[0][1], a[0][2], a[0][3], b0, b1);
                mma16(acc[1][nt], a[1][0], a[1][1], a[1][2], a[1][3], b0, b1);
            }
        }
    }
    __syncthreads();

    __half* T = smh;
    #pragma unroll
    for (int mt = 0; mt < 2; mt++) {
        #pragma unroll
        for (int nt = 0; nt < 6; nt++) {
            const int n = colq * 48 + nt * 8 + 2 * tg;
            const int r0 = rbase + rp * 32 + mt * 16;
            if (n < 64) {
                *(uint32_t*)&g_Qh[(size_t)(r0 + g    ) * DDIM + n] =
                    hpack(acc[mt][nt][0], acc[mt][nt][1]);
                *(uint32_t*)&g_Qh[(size_t)(r0 + g + 8) * DDIM + n] =
                    hpack(acc[mt][nt][2], acc[mt][nt][3]);
            } else if (n < 128) {
                *(uint32_t*)&g_Kh[(size_t)(r0 + g    ) * DDIM + n - 64] =
                    hpack(acc[mt][nt][0], acc[mt][nt][1]);
                *(uint32_t*)&g_Kh[(size_t)(r0 + g + 8) * DDIM + n - 64] =
                    hpack(acc[mt][nt][2], acc[mt][nt][3]);
            } else {
                const int d = n - 128;
                const int s0 = rp * 32 + mt * 16;
                T[(d    ) * 72 + s0 + g    ] = __float2half_rn(acc[mt][nt][0]);
                T[(d + 1) * 72 + s0 + g    ] = __float2half_rn(acc[mt][nt][1]);
                T[(d    ) * 72 + s0 + g + 8] = __float2half_rn(acc[mt][nt][2]);
                T[(d + 1) * 72 + s0 + g + 8] = __float2half_rn(acc[mt][nt][3]);
            }
        }
    }
    __syncthreads();
    {
        const int b = rbase >> 12;
        const int sbase = rbase & 4095;
        #pragma unroll
        for (int i = 0; i < 2; i++) {
            int idx = tid + i * 256;
            int d = idx >> 3, c8 = idx & 7;
            uint4 v = *(const uint4*)&T[d * 72 + c8 * 8];
            *(uint4*)&g_VTh[((size_t)b * DDIM + d) * SEQ + sbase + c8 * 8] = v;
        }
    }
}

// ---------------------------------------------------------------------------
// fp16 mma flash attention: 4 warps x 32 query rows, split-K=2, 2 CTAs/SM.
// grid (SEQ/128, B, NSPLIT), block 128. Q fragments in registers.
// P = exp(S) never touches smem: the PV A-fragment is two packed S C-fragments.
// SMEM bytes: K[2][9216] V[2][9216] = 36864 B only.
// ---------------------------------------------------------------------------
#define KB_OFF 0
#define VB_OFF 18432
#define SMEM_ATTN 36864

__global__ __launch_bounds__(128, 2) void attn_mma()
{
    extern __shared__ __half smah[];
    char* smb = (char*)smah;
    const uint32_t smem_u32 = (uint32_t)__cvta_generic_to_shared(smb);

    const int tid  = threadIdx.x;
    const int lane = tid & 31;
    const int wid  = tid >> 5;          // 0..3
    const int g  = lane >> 2;
    const int tg = lane & 3;
    const int b     = blockIdx.y;
    const int split = blockIdx.z;
    const int qbase = blockIdx.x * 128;
    const int qrow0 = wid * 32;

    // ---- Q fragments straight from global (fp16, pre-scaled): 32 regs ----
    const __half* Qg = g_Qh + ((size_t)b * SEQ + qbase + qrow0) * DDIM;
    uint32_t qa[2][4][4];
    #pragma unroll
    for (int mt = 0; mt < 2; mt++) {
        #pragma unroll
        for (int ks = 0; ks < 4; ks++) {
            const int kcol = ks * 16 + 2 * tg;
            qa[mt][ks][0] = *(const uint32_t*)&Qg[(size_t)(mt * 16 + g    ) * DDIM + kcol];
            qa[mt][ks][1] = *(const uint32_t*)&Qg[(size_t)(mt * 16 + g + 8) * DDIM + kcol];
            qa[mt][ks][2] = *(const uint32_t*)&Qg[(size_t)(mt * 16 + g    ) * DDIM + kcol + 8];
            qa[mt][ks][3] = *(const uint32_t*)&Qg[(size_t)(mt * 16 + g + 8) * DDIM + kcol + 8];
        }
    }

    float oacc[2][8][4];
    float lrow[4] = {0.f, 0.f, 0.f, 0.f};
    #pragma unroll
    for (int mt = 0; mt < 2; mt++)
        #pragma unroll
        for (int nt = 0; nt < 8; nt++)
            #pragma unroll
            for (int e = 0; e < 4; e++) oacc[mt][nt][e] = 0.f;

    const __half* Kb = g_Kh + ((size_t)b * SEQ + (size_t)split * (SEQ / NSPLIT)) * DDIM;
    const __half* Vb = g_VTh + (size_t)b * DDIM * SEQ + (size_t)split * (SEQ / NSPLIT);

    // fill coords: 64 rows x 8 chunks of 16B per tensor; 128 threads x 4 each
    const int frow = tid >> 1;
    const int fc   = (tid & 1) * 4;

    // prologue: tile 0 into buffer 0
    #pragma unroll
    for (int c = 0; c < 4; c++) {
        cp16(smem_u32 + KB_OFF + frow * 144 + (fc + c) * 16,
             (const char*)Kb + frow * 128 + (fc + c) * 16);
        cp16(smem_u32 + VB_OFF + frow * 144 + (fc + c) * 16,
             (const char*)Vb + (size_t)frow * (SEQ * 2) + (fc + c) * 16);
    }
    CP_COMMIT();

    #pragma unroll 1
    for (int kt = 0; kt < KT_PER; kt++) {
        // async-fill next tile (buffer released by trailing barrier of kt-1)
        {
            int nk = (kt + 1 < KT_PER) ? kt + 1 : kt;
            int nb = (kt + 1) & 1;
            const char* Kg = (const char*)(Kb + (size_t)nk * 64 * DDIM);
            const char* Vg = (const char*)(Vb + (size_t)nk * 64);
            #pragma unroll
            for (int c = 0; c < 4; c++) {
                cp16(smem_u32 + KB_OFF + nb * 9216 + frow * 144 + (fc + c) * 16,
                     Kg + frow * 128 + (fc + c) * 16);
                cp16(smem_u32 + VB_OFF + nb * 9216 + frow * 144 + (fc + c) * 16,
                     Vg + (size_t)frow * (SEQ * 2) + (fc + c) * 16);
            }
            CP_COMMIT();
        }
        CP_WAIT1();
        __syncthreads();

        const __half* Ks = (const __half*)(smb + KB_OFF) + (kt & 1) * 4608;
        const __half* Vs = (const __half*)(smb + VB_OFF) + (kt & 1) * 4608;

        // ---- S = Q @ K^T : both mtiles share every K B-fragment ----
        float sacc[2][8][4];
        #pragma unroll
        for (int mt = 0; mt < 2; mt++)
            #pragma unroll
            for (int nt = 0; nt < 8; nt++)
                #pragma unroll
                for (int e = 0; e < 4; e++) sacc[mt][nt][e] = 0.f;

        #pragma unroll
        for (int ks = 0; ks < 4; ks++) {
            const int kcol = ks * 16 + 2 * tg;
            #pragma unroll
            for (int nt = 0; nt < 8; nt++) {
                uint32_t b0 = LDSH2(&Ks[(nt * 8 + g) * 72 + kcol]);
                uint32_t b1 = LDSH2(&Ks[(nt * 8 + g) * 72 + kcol + 8]);
                mma16(sacc[0][nt], qa[0][ks][0], qa[0][ks][1], qa[0][ks][2], qa[0][ks][3], b0, b1);
                mma16(sacc[1][nt], qa[1][ks][0], qa[1][ks][1], qa[1][ks][2], qa[1][ks][3], b0, b1);
            }
        }

        // ---- P = 2^S packed directly into PV A-fragments (no smem!) ----
        // PV k-step ks2 covers keys ks2*16..+15 = S ntiles 2*ks2 and 2*ks2+1:
        //   a0 = {P[g][2tg],P[g][2tg+1]} of nt=2ks2   = pack(c0,c1)
        //   a1 = rows g+8 of nt=2ks2                  = pack(c2,c3)
        //   a2 = nt=2ks2+1 rows g                     = pack(c0,c1)
        //   a3 = nt=2ks2+1 rows g+8                   = pack(c2,c3)
        uint32_t p[2][4][4];
        #pragma unroll
        for (int mt = 0; mt < 2; mt++) {
            #pragma unroll
            for (int ks2 = 0; ks2 < 4; ks2++) {
                const int na = 2 * ks2, nb2 = 2 * ks2 + 1;
                float ea0 = ex2(sacc[mt][na][0]),  ea1 = ex2(sacc[mt][na][1]);
                float ea2 = ex2(sacc[mt][na][2]),  ea3 = ex2(sacc[mt][na][3]);
                float eb0 = ex2(sacc[mt][nb2][0]), eb1 = ex2(sacc[mt][nb2][1]);
                float eb2 = ex2(sacc[mt][nb2][2]), eb3 = ex2(sacc[mt][nb2][3]);
                lrow[mt * 2 + 0] += (ea0 + ea1) + (eb0 + eb1);
                lrow[mt * 2 + 1] += (ea2 + ea3) + (eb2 + eb3);
                p[mt][ks2][0] = hpack(ea0, ea1);
                p[mt][ks2][1] = hpack(ea2, ea3);
                p[mt][ks2][2] = hpack(eb0, eb1);
                p[mt][ks2][3] = hpack(eb2, eb3);
            }
        }

        // ---- O += P @ V : both mtiles share every V B-fragment ----
        #pragma unroll
        for (int ks2 = 0; ks2 < 4; ks2++) {
            const int kcol = ks2 * 16 + 2 * tg;
            #pragma unroll
            for (int nt = 0; nt < 8; nt++) {
                uint32_t b0 = LDSH2(&Vs[(nt * 8 + g) * 72 + kcol]);
                uint32_t b1 = LDSH2(&Vs[(nt * 8 + g) * 72 + kcol + 8]);
                mma16(oacc[0][nt], p[0][ks2][0], p[0][ks2][1], p[0][ks2][2], p[0][ks2][3], b0, b1);
                mma16(oacc[1][nt], p[1][ks2][0], p[1][ks2][1], p[1][ks2][2], p[1][ks2][3], b0, b1);
            }
        }
        __syncthreads();   // release buffer kt&1 before iter kt+1 overwrites it
    }

    // ---- quad-reduce row sums ----
    #pragma unroll
    for (int i = 0; i < 4; i++) {
        lrow[i] += __shfl_xor_sync(0xffffffffu, lrow[i], 1);
        lrow[i] += __shfl_xor_sync(0xffffffffu, lrow[i], 2);
    }

    // ---- store unnormalized partials ----
    const size_t rbase = (size_t)split * M_TOTAL + (size_t)b * SEQ + qbase + qrow0;
    #pragma unroll
    for (int mt = 0; mt < 2; mt++) {
        #pragma unroll
        for (int nt = 0; nt < 8; nt++) {
            float2 o0, o1;
            o0.x = oacc[mt][nt][0]; o0.y = oacc[mt][nt][1];
            o1.x = oacc[mt][nt][2]; o1.y = oacc[mt][nt][3];
            *(float2*)&g_Opart[(rbase + mt * 16 + g    ) * DDIM + nt * 8 + 2 * tg] = o0;
            *(float2*)&g_Opart[(rbase + mt * 16 + 8 + g) * DDIM + nt * 8 + 2 * tg] = o1;
        }
    }
    if (tg == 0) {
        g_Lpart[rbase + g]          = lrow[0];
        g_Lpart[rbase + g + 8]      = lrow[1];
        g_Lpart[rbase + 16 + g]     = lrow[2];
        g_Lpart[rbase + 16 + g + 8] = lrow[3];
    }
}

// ---------------------------------------------------------------------------
// Combine: out = (O0 + O1) / (l0 + l1)
// ---------------------------------------------------------------------------
__global__ __launch_bounds__(256) void combine(float* __restrict__ out)
{
    const int i = blockIdx.x * 256 + threadIdx.x;
    const int row = i >> 4;
    const float inv = 1.0f / (g_Lpart[row] + g_Lpart[M_TOTAL + row]);
    const float4 a = *(const float4*)&g_Opart[(size_t)i * 4];
    const float4 c = *(const float4*)&g_Opart[(size_t)M_TOTAL * DDIM + (size_t)i * 4];
    float4 r;
    r.x = (a.x + c.x) * inv;
    r.y = (a.y + c.y) * inv;
    r.z = (a.z + c.z) * inv;
    r.w = (a.w + c.w) * inv;
    *(float4*)&out[(size_t)i * 4] = r;
}

// ---------------------------------------------------------------------------
extern "C" void kernel_launch(void* const* d_in, const int* in_sizes, int n_in,
                              void* d_out, int out_size)
{
    const float* x  = (const float*)d_in[0];
    const float* Wq = (const float*)d_in[1];
    const float* Wk = (const float*)d_in[2];
    const float* Wv = (const float*)d_in[3];
    float* out = (float*)d_out;

    cudaFuncSetAttribute(qkv_tc,   cudaFuncAttributeMaxDynamicSharedMemorySize, SMEM_QKV);
    cudaFuncSetAttribute(attn_mma, cudaFuncAttributeMaxDynamicSharedMemorySize, SMEM_ATTN);

    prep_w<<<192 * FDIM / 256, 256>>>(Wq, Wk, Wv);
    qkv_tc<<<M_TOTAL / 64, 256, SMEM_QKV>>>(x);
    attn_mma<<<dim3(SEQ / 128, BS, NSPLIT), 128, SMEM_ATTN>>>();
    combine<<<(M_TOTAL * DDIM / 4) / 256, 256>>>(out);
}

// round 11
// speedup vs baseline: 1.1837x; 1.0452x over previous
#include <cuda_runtime.h>
#include <cuda_fp16.h>
#include <cstdint>

#define BS   4
#define SEQ  4096
#define FDIM 512
#define DDIM 64
#define M_TOTAL (BS*SEQ)
#define NSPLIT 2
#define KT_PER (SEQ / 64 / NSPLIT)   // 32

// fp16 projected tensors: Q (scaled 0.125*log2e) [b,s,d], K [b,s,d], V^T [b,d,s]
__device__ __half g_Qh[(size_t)M_TOTAL * DDIM];
__device__ __half g_Kh[(size_t)M_TOTAL * DDIM];
__device__ __half g_VTh[(size_t)BS * DDIM * SEQ];
// fp16 transposed weights: rows n (0-63 Q, 64-127 K, 128-191 V), cols k (512)
__device__ __half g_WT[192 * FDIM];
// Split-K partials
__device__ float g_Opart[NSPLIT * (size_t)M_TOTAL * DDIM];
__device__ float g_Lpart[NSPLIT * M_TOTAL];

// ---------------------------------------------------------------------------
// helpers
// ---------------------------------------------------------------------------
__device__ __forceinline__ uint32_t hpack(float a, float b) {
    __half2 h = __floats2half2_rn(a, b);
    return *(uint32_t*)&h;
}
// pack two fp32 to half2 (lo, hi) in one cvt
__device__ __forceinline__ uint32_t pack2(float lo, float hi) {
    uint32_t u;
    asm("cvt.rn.f16x2.f32 %0, %1, %2;" : "=r"(u) : "f"(hi), "f"(lo));
    return u;
}
// 2^x on both fp16 halves in one MUFU op
__device__ __forceinline__ uint32_t ex2h2(uint32_t x) {
    uint32_t y;
    asm("ex2.approx.f16x2 %0, %1;" : "=r"(y) : "r"(x));
    return y;
}
__device__ __forceinline__ void mma16(float* d,
                                      uint32_t a0, uint32_t a1, uint32_t a2, uint32_t a3,
                                      uint32_t b0, uint32_t b1) {
    asm volatile("mma.sync.aligned.m16n8k16.row.col.f32.f16.f16.f32 "
        "{%0,%1,%2,%3}, {%4,%5,%6,%7}, {%8,%9}, {%0,%1,%2,%3};"
        : "+f"(d[0]), "+f"(d[1]), "+f"(d[2]), "+f"(d[3])
        : "r"(a0), "r"(a1), "r"(a2), "r"(a3), "r"(b0), "r"(b1));
}
__device__ __forceinline__ uint32_t LDSH2(const __half* p) {
    return *(const uint32_t*)p;
}
__device__ __forceinline__ void cp16(uint32_t s, const void* g) {
    asm volatile("cp.async.ca.shared.global [%0], [%1], 16;" :: "r"(s), "l"(g) : "memory");
}
#define CP_COMMIT() asm volatile("cp.async.commit_group;" ::: "memory")
#define CP_WAIT0()  asm volatile("cp.async.wait_group 0;" ::: "memory")
#define CP_WAIT1()  asm volatile("cp.async.wait_group 1;" ::: "memory")
#define ONES_H2 0x3C003C00u

// ---------------------------------------------------------------------------
// prep_w: W{q,k,v} fp32 [512,64] -> g_WT fp16 [192][512] (transposed),
// Q-scale 0.125*log2e folded into rows 0-63.
// ---------------------------------------------------------------------------
__global__ __launch_bounds__(256) void prep_w(
    const float* __restrict__ Wq,
    const float* __restrict__ Wk,
    const float* __restrict__ Wv)
{
    const int idx = blockIdx.x * 256 + threadIdx.x;
    const int n = idx >> 9;
    const int k = idx & 511;
    const float* W = (n < 64) ? Wq : ((n < 128) ? Wk : Wv);
    const float s = (n < 64) ? 0.125f * 1.44269504f : 1.0f;
    g_WT[idx] = __float2half_rn(W[(size_t)k * DDIM + (n & 63)] * s);
}

// ---------------------------------------------------------------------------
// Fused QKV projection, plain fp16 tensor GEMM. (unchanged)
// ---------------------------------------------------------------------------
#define QXS 0
#define QWS 9216
#define SMEM_QKV ((9216 + 27648) * 2)

__global__ __launch_bounds__(256, 2) void qkv_tc(const float* __restrict__ x)
{
    extern __shared__ __half smh[];
    const uint32_t smem_u32 = (uint32_t)__cvta_generic_to_shared(smh);

    const int rbase = blockIdx.x * 64;
    const int tid  = threadIdx.x;
    const int lane = tid & 31;
    const int wid  = tid >> 5;
    const int g  = lane >> 2;
    const int tg = lane & 3;
    const int rp   = wid & 1;
    const int colq = wid >> 1;

    const int xrow = tid >> 2;
    const int xc16 = (tid & 3) * 16;

    float acc[2][6][4];
    #pragma unroll
    for (int mt = 0; mt < 2; mt++)
        #pragma unroll
        for (int nt = 0; nt < 6; nt++)
            #pragma unroll
            for (int e = 0; e < 4; e++) acc[mt][nt][e] = 0.f;

    #pragma unroll
    for (int i = 0; i < 6; i++) {
        int idx = tid + i * 256;
        int row = idx >> 3, c = idx & 7;
        cp16(smem_u32 + QWS * 2 + row * 144 + c * 16,
             (const char*)g_WT + (size_t)row * FDIM * 2 + c * 16);
    }
    CP_COMMIT();

    float4 xr[4];
    #pragma unroll
    for (int i = 0; i < 4; i++)
        xr[i] = *(const float4*)&x[(size_t)(rbase + xrow) * FDIM + xc16 + i * 4];

    #pragma unroll 1
    for (int kc = 0; kc < 8; kc++) {
        const int buf = kc & 1;
        __half* Xs = smh + QXS + buf * 4608;
        const __half* Ws = smh + QWS + buf * 13824;

        {
            uint4 u0, u1;
            u0.x = hpack(xr[0].x, xr[0].y); u0.y = hpack(xr[0].z, xr[0].w);
            u0.z = hpack(xr[1].x, xr[1].y); u0.w = hpack(xr[1].z, xr[1].w);
            u1.x = hpack(xr[2].x, xr[2].y); u1.y = hpack(xr[2].z, xr[2].w);
            u1.z = hpack(xr[3].x, xr[3].y); u1.w = hpack(xr[3].z, xr[3].w);
            *(uint4*)&Xs[xrow * 72 + xc16]     = u0;
            *(uint4*)&Xs[xrow * 72 + xc16 + 8] = u1;
        }
        if (kc < 7) {
            #pragma unroll
            for (int i = 0; i < 4; i++)
                xr[i] = *(const float4*)&x[(size_t)(rbase + xrow) * FDIM
                                           + (kc + 1) * 64 + xc16 + i * 4];
        }

        CP_WAIT0();
        __syncthreads();

        if (kc < 7) {
            const int nb = (kc + 1) & 1;
            #pragma unroll
            for (int i = 0; i < 6; i++) {
                int idx = tid + i * 256;
                int row = idx >> 3, c = idx & 7;
                cp16(smem_u32 + QWS * 2 + nb * 27648 + row * 144 + c * 16,
                     (const char*)g_WT + (size_t)row * FDIM * 2 + (kc + 1) * 128 + c * 16);
            }
            CP_COMMIT();
        }

        #pragma unroll
        for (int ks = 0; ks < 4; ks++) {
            const int kcol = ks * 16 + 2 * tg;
            uint32_t a[2][4];
            #pragma unroll
            for (int mt = 0; mt < 2; mt++) {
                const int r0 = rp * 32 + mt * 16;
                a[mt][0] = LDSH2(&Xs[(r0 + g    ) * 72 + kcol]);
                a[mt][1] = LDSH2(&Xs[(r0 + g + 8) * 72 + kcol]);
                a[mt][2] = LDSH2(&Xs[(r0 + g    ) * 72 + kcol + 8]);
                a[mt][3] = LDSH2(&Xs[(r0 + g + 8) * 72 + kcol + 8]);
            }
            #pragma unroll
            for (int nt = 0; nt < 6; nt++) {
                const int n = colq * 48 + nt * 8 + g;
                uint32_t b0 = LDSH2(&Ws[n * 72 + kcol]);
                uint32_t b1 = LDSH2(&Ws[n * 72 + kcol + 8]);
                mma16(acc[0][nt], a[0][0], a[0][1], a[0][2], a[0][3], b0, b1);
                mma16(acc[1][nt], a[1][0], a[1][1], a[1][2], a[1][3], b0, b1);
            }
        }
    }
    __syncthreads();

    __half* T = smh;
    #pragma unroll
    for (int mt = 0; mt < 2; mt++) {
        #pragma unroll
        for (int nt = 0; nt < 6; nt++) {
            const int n = colq * 48 + nt * 8 + 2 * tg;
            const int r0 = rbase + rp * 32 + mt * 16;
            if (n < 64) {
                *(uint32_t*)&g_Qh[(size_t)(r0 + g    ) * DDIM + n] =
                    hpack(acc[mt][nt][0], acc[mt][nt][1]);
                *(uint32_t*)&g_Qh[(size_t)(r0 + g + 8) * DDIM + n] =
                    hpack(acc[mt][nt][2], acc[mt][nt][3]);
            } else if (n < 128) {
                *(uint32_t*)&g_Kh[(size_t)(r0 + g    ) * DDIM + n - 64] =
                    hpack(acc[mt][nt][0], acc[mt][nt][1]);
                *(uint32_t*)&g_Kh[(size_t)(r0 + g + 8) * DDIM + n - 64] =
                    hpack(acc[mt][nt][2], acc[mt][nt][3]);
            } else {
                const int d = n - 128;
                const int s0 = rp * 32 + mt * 16;
                T[(d    ) * 72 + s0 + g    ] = __float2half_rn(acc[mt][nt][0]);
                T[(d + 1) * 72 + s0 + g    ] = __float2half_rn(acc[mt][nt][1]);
                T[(d    ) * 72 + s0 + g + 8] = __float2half_rn(acc[mt][nt][2]);
                T[(d + 1) * 72 + s0 + g + 8] = __float2half_rn(acc[mt][nt][3]);
            }
        }
    }
    __syncthreads();
    {
        const int b = rbase >> 12;
        const int sbase = rbase & 4095;
        #pragma unroll
        for (int i = 0; i < 2; i++) {
            int idx = tid + i * 256;
            int d = idx >> 3, c8 = idx & 7;
            uint4 v = *(const uint4*)&T[d * 72 + c8 * 8];
            *(uint4*)&g_VTh[((size_t)b * DDIM + d) * SEQ + sbase + c8 * 8] = v;
        }
    }
}

// ---------------------------------------------------------------------------
// fp16 mma flash attention: 4 warps x 32 query rows, split-K=2, 2 CTAs/SM.
// P = ex2.f16x2(S) packed directly into PV A-fragments (no smem, 1 MUFU/pair).
// Row sums l computed by tensor core: extra MMA against constant ones-B.
// SMEM bytes: K[2][9216] V[2][9216] = 36864 B.
// ---------------------------------------------------------------------------
#define KB_OFF 0
#define VB_OFF 18432
#define SMEM_ATTN 36864

__global__ __launch_bounds__(128, 2) void attn_mma()
{
    extern __shared__ __half smah[];
    char* smb = (char*)smah;
    const uint32_t smem_u32 = (uint32_t)__cvta_generic_to_shared(smb);

    const int tid  = threadIdx.x;
    const int lane = tid & 31;
    const int wid  = tid >> 5;          // 0..3
    const int g  = lane >> 2;
    const int tg = lane & 3;
    const int b     = blockIdx.y;
    const int split = blockIdx.z;
    const int qbase = blockIdx.x * 128;
    const int qrow0 = wid * 32;

    // ---- Q fragments straight from global (fp16, pre-scaled): 32 regs ----
    const __half* Qg = g_Qh + ((size_t)b * SEQ + qbase + qrow0) * DDIM;
    uint32_t qa[2][4][4];
    #pragma unroll
    for (int mt = 0; mt < 2; mt++) {
        #pragma unroll
        for (int ks = 0; ks < 4; ks++) {
            const int kcol = ks * 16 + 2 * tg;
            qa[mt][ks][0] = *(const uint32_t*)&Qg[(size_t)(mt * 16 + g    ) * DDIM + kcol];
            qa[mt][ks][1] = *(const uint32_t*)&Qg[(size_t)(mt * 16 + g + 8) * DDIM + kcol];
            qa[mt][ks][2] = *(const uint32_t*)&Qg[(size_t)(mt * 16 + g    ) * DDIM + kcol + 8];
            qa[mt][ks][3] = *(const uint32_t*)&Qg[(size_t)(mt * 16 + g + 8) * DDIM + kcol + 8];
        }
    }

    float oacc[2][8][4];
    float lacc[2][4];                    // row sums via ones-MMA
    #pragma unroll
    for (int mt = 0; mt < 2; mt++) {
        #pragma unroll
        for (int nt = 0; nt < 8; nt++)
            #pragma unroll
            for (int e = 0; e < 4; e++) oacc[mt][nt][e] = 0.f;
        #pragma unroll
        for (int e = 0; e < 4; e++) lacc[mt][e] = 0.f;
    }

    const __half* Kb = g_Kh + ((size_t)b * SEQ + (size_t)split * (SEQ / NSPLIT)) * DDIM;
    const __half* Vb = g_VTh + (size_t)b * DDIM * SEQ + (size_t)split * (SEQ / NSPLIT);

    const int frow = tid >> 1;
    const int fc   = (tid & 1) * 4;

    // prologue: tile 0 into buffer 0
    #pragma unroll
    for (int c = 0; c < 4; c++) {
        cp16(smem_u32 + KB_OFF + frow * 144 + (fc + c) * 16,
             (const char*)Kb + frow * 128 + (fc + c) * 16);
        cp16(smem_u32 + VB_OFF + frow * 144 + (fc + c) * 16,
             (const char*)Vb + (size_t)frow * (SEQ * 2) + (fc + c) * 16);
    }
    CP_COMMIT();

    #pragma unroll 1
    for (int kt = 0; kt < KT_PER; kt++) {
        // async-fill next tile (buffer released by trailing barrier of kt-1)
        {
            int nk = (kt + 1 < KT_PER) ? kt + 1 : kt;
            int nb = (kt + 1) & 1;
            const char* Kg = (const char*)(Kb + (size_t)nk * 64 * DDIM);
            const char* Vg = (const char*)(Vb + (size_t)nk * 64);
            #pragma unroll
            for (int c = 0; c < 4; c++) {
                cp16(smem_u32 + KB_OFF + nb * 9216 + frow * 144 + (fc + c) * 16,
                     Kg + frow * 128 + (fc + c) * 16);
                cp16(smem_u32 + VB_OFF + nb * 9216 + frow * 144 + (fc + c) * 16,
                     Vg + (size_t)frow * (SEQ * 2) + (fc + c) * 16);
            }
            CP_COMMIT();
        }
        CP_WAIT1();
        __syncthreads();

        const __half* Ks = (const __half*)(smb + KB_OFF) + (kt & 1) * 4608;
        const __half* Vs = (const __half*)(smb + VB_OFF) + (kt & 1) * 4608;

        // ---- S = Q @ K^T : both mtiles share every K B-fragment ----
        float sacc[2][8][4];
        #pragma unroll
        for (int mt = 0; mt < 2; mt++)
            #pragma unroll
            for (int nt = 0; nt < 8; nt++)
                #pragma unroll
                for (int e = 0; e < 4; e++) sacc[mt][nt][e] = 0.f;

        #pragma unroll
        for (int ks = 0; ks < 4; ks++) {
            const int kcol = ks * 16 + 2 * tg;
            #pragma unroll
            for (int nt = 0; nt < 8; nt++) {
                uint32_t b0 = LDSH2(&Ks[(nt * 8 + g) * 72 + kcol]);
                uint32_t b1 = LDSH2(&Ks[(nt * 8 + g) * 72 + kcol + 8]);
                mma16(sacc[0][nt], qa[0][ks][0], qa[0][ks][1], qa[0][ks][2], qa[0][ks][3], b0, b1);
                mma16(sacc[1][nt], qa[1][ks][0], qa[1][ks][1], qa[1][ks][2], qa[1][ks][3], b0, b1);
            }
        }

        // ---- P = 2^S via f16x2 MUFU, packed directly into PV A-fragments ----
        uint32_t p[2][4][4];
        #pragma unroll
        for (int mt = 0; mt < 2; mt++) {
            #pragma unroll
            for (int ks2 = 0; ks2 < 4; ks2++) {
                const int na = 2 * ks2, nb2 = 2 * ks2 + 1;
                p[mt][ks2][0] = ex2h2(pack2(sacc[mt][na][0],  sacc[mt][na][1]));
                p[mt][ks2][1] = ex2h2(pack2(sacc[mt][na][2],  sacc[mt][na][3]));
                p[mt][ks2][2] = ex2h2(pack2(sacc[mt][nb2][0], sacc[mt][nb2][1]));
                p[mt][ks2][3] = ex2h2(pack2(sacc[mt][nb2][2], sacc[mt][nb2][3]));
            }
        }

        // ---- O += P @ V ; l += P @ 1 (constant ones B fragment, no LDS) ----
        #pragma unroll
        for (int ks2 = 0; ks2 < 4; ks2++) {
            const int kcol = ks2 * 16 + 2 * tg;
            #pragma unroll
            for (int nt = 0; nt < 8; nt++) {
                uint32_t b0 = LDSH2(&Vs[(nt * 8 + g) * 72 + kcol]);
                uint32_t b1 = LDSH2(&Vs[(nt * 8 + g) * 72 + kcol + 8]);
                mma16(oacc[0][nt], p[0][ks2][0], p[0][ks2][1], p[0][ks2][2], p[0][ks2][3], b0, b1);
                mma16(oacc[1][nt], p[1][ks2][0], p[1][ks2][1], p[1][ks2][2], p[1][ks2][3], b0, b1);
            }
            mma16(lacc[0], p[0][ks2][0], p[0][ks2][1], p[0][ks2][2], p[0][ks2][3],
                  ONES_H2, ONES_H2);
            mma16(lacc[1], p[1][ks2][0], p[1][ks2][1], p[1][ks2][2], p[1][ks2][3],
                  ONES_H2, ONES_H2);
        }
        __syncthreads();   // release buffer kt&1 before iter kt+1 overwrites it
    }

    // ---- store unnormalized partials (lacc identical across tg lanes) ----
    const size_t rbase = (size_t)split * M_TOTAL + (size_t)b * SEQ + qbase + qrow0;
    #pragma unroll
    for (int mt = 0; mt < 2; mt++) {
        #pragma unroll
        for (int nt = 0; nt < 8; nt++) {
            float2 o0, o1;
            o0.x = oacc[mt][nt][0]; o0.y = oacc[mt][nt][1];
            o1.x = oacc[mt][nt][2]; o1.y = oacc[mt][nt][3];
            *(float2*)&g_Opart[(rbase + mt * 16 + g    ) * DDIM + nt * 8 + 2 * tg] = o0;
            *(float2*)&g_Opart[(rbase + mt * 16 + 8 + g) * DDIM + nt * 8 + 2 * tg] = o1;
        }
    }
    if (tg == 0) {
        g_Lpart[rbase + g]          = lacc[0][0];
        g_Lpart[rbase + g + 8]      = lacc[0][2];
        g_Lpart[rbase + 16 + g]     = lacc[1][0];
        g_Lpart[rbase + 16 + g + 8] = lacc[1][2];
    }
}

// ---------------------------------------------------------------------------
// Combine: out = (O0 + O1) / (l0 + l1), 2 float4 per thread for MLP
// ---------------------------------------------------------------------------
__global__ __launch_bounds__(256) void combine(float* __restrict__ out)
{
    const int i = blockIdx.x * 256 + threadIdx.x;   // pair index
    const int row = i >> 3;                          // 8 pairs per row
    const float inv = 1.0f / (g_Lpart[row] + g_Lpart[M_TOTAL + row]);
    #pragma unroll
    for (int h = 0; h < 2; h++) {
        const size_t e = (size_t)i * 8 + h * 4;
        const float4 a = *(const float4*)&g_Opart[e];
        const float4 c = *(const float4*)&g_Opart[(size_t)M_TOTAL * DDIM + e];
        float4 r;
        r.x = (a.x + c.x) * inv;
        r.y = (a.y + c.y) * inv;
        r.z = (a.z + c.z) * inv;
        r.w = (a.w + c.w) * inv;
        *(float4*)&out[e] = r;
    }
}

// ---------------------------------------------------------------------------
extern "C" void kernel_launch(void* const* d_in, const int* in_sizes, int n_in,
                              void* d_out, int out_size)
{
    const float* x  = (const float*)d_in[0];
    const float* Wq = (const float*)d_in[1];
    const float* Wk = (const float*)d_in[2];
    const float* Wv = (const float*)d_in[3];
    float* out = (float*)d_out;

    cudaFuncSetAttribute(qkv_tc,   cudaFuncAttributeMaxDynamicSharedMemorySize, SMEM_QKV);
    cudaFuncSetAttribute(attn_mma, cudaFuncAttributeMaxDynamicSharedMemorySize, SMEM_ATTN);

    prep_w<<<192 * FDIM / 256, 256>>>(Wq, Wk, Wv);
    qkv_tc<<<M_TOTAL / 64, 256, SMEM_QKV>>>(x);
    attn_mma<<<dim3(SEQ / 128, BS, NSPLIT), 128, SMEM_ATTN>>>();
    combine<<<(M_TOTAL * DDIM / 8) / 256, 256>>>(out);
}

// round 12
// speedup vs baseline: 1.1896x; 1.0050x over previous
#include <cuda_runtime.h>
#include <cuda_fp16.h>
#include <cstdint>

#define BS   4
#define SEQ  4096
#define FDIM 512
#define DDIM 64
#define M_TOTAL (BS*SEQ)
#define NSPLIT 2
#define KT_PER (SEQ / 64 / NSPLIT)   // 32

// fp16 projected tensors: Q (scaled 0.125*log2e) [b,s,d], K [b,s,d], V^T [b,d,s]
__device__ __half g_Qh[(size_t)M_TOTAL * DDIM];
__device__ __half g_Kh[(size_t)M_TOTAL * DDIM];
__device__ __half g_VTh[(size_t)BS * DDIM * SEQ];
// fp16 transposed weights: rows n (0-63 Q, 64-127 K, 128-191 V), cols k (512)
__device__ __half g_WT[192 * FDIM];
// Split-K partials
__device__ float g_Opart[NSPLIT * (size_t)M_TOTAL * DDIM];
__device__ float g_Lpart[NSPLIT * M_TOTAL];

// ---------------------------------------------------------------------------
// helpers
// ---------------------------------------------------------------------------
__device__ __forceinline__ uint32_t hpack(float a, float b) {
    __half2 h = __floats2half2_rn(a, b);
    return *(uint32_t*)&h;
}
__device__ __forceinline__ uint32_t pack2(float lo, float hi) {
    uint32_t u;
    asm("cvt.rn.f16x2.f32 %0, %1, %2;" : "=r"(u) : "f"(hi), "f"(lo));
    return u;
}
__device__ __forceinline__ uint32_t ex2h2(uint32_t x) {
    uint32_t y;
    asm("ex2.approx.f16x2 %0, %1;" : "=r"(y) : "r"(x));
    return y;
}
__device__ __forceinline__ void mma16(float* d,
                                      uint32_t a0, uint32_t a1, uint32_t a2, uint32_t a3,
                                      uint32_t b0, uint32_t b1) {
    asm volatile("mma.sync.aligned.m16n8k16.row.col.f32.f16.f16.f32 "
        "{%0,%1,%2,%3}, {%4,%5,%6,%7}, {%8,%9}, {%0,%1,%2,%3};"
        : "+f"(d[0]), "+f"(d[1]), "+f"(d[2]), "+f"(d[3])
        : "r"(a0), "r"(a1), "r"(a2), "r"(a3), "r"(b0), "r"(b1));
}
__device__ __forceinline__ uint32_t LDSH2(const __half* p) {
    return *(const uint32_t*)p;
}
__device__ __forceinline__ void cp16(uint32_t s, const void* g) {
    asm volatile("cp.async.ca.shared.global [%0], [%1], 16;" :: "r"(s), "l"(g) : "memory");
}
#define CP_COMMIT() asm volatile("cp.async.commit_group;" ::: "memory")
#define CP_WAIT0()  asm volatile("cp.async.wait_group 0;" ::: "memory")
#define CP_WAIT1()  asm volatile("cp.async.wait_group 1;" ::: "memory")
#define ONES_H2 0x3C003C00u

// ---------------------------------------------------------------------------
// prep_w: W{q,k,v} fp32 [512,64] -> g_WT fp16 [192][512] (transposed),
// Q-scale 0.125*log2e folded into rows 0-63.
// ---------------------------------------------------------------------------
__global__ __launch_bounds__(256) void prep_w(
    const float* __restrict__ Wq,
    const float* __restrict__ Wk,
    const float* __restrict__ Wv)
{
    const int idx = blockIdx.x * 256 + threadIdx.x;
    const int n = idx >> 9;
    const int k = idx & 511;
    const float* W = (n < 64) ? Wq : ((n < 128) ? Wk : Wv);
    const float s = (n < 64) ? 0.125f * 1.44269504f : 1.0f;
    g_WT[idx] = __float2half_rn(W[(size_t)k * DDIM + (n & 63)] * s);
}

// ---------------------------------------------------------------------------
// Fused QKV projection, plain fp16 tensor GEMM. (unchanged)
// ---------------------------------------------------------------------------
#define QXS 0
#define QWS 9216
#define SMEM_QKV ((9216 + 27648) * 2)

__global__ __launch_bounds__(256, 2) void qkv_tc(const float* __restrict__ x)
{
    extern __shared__ __half smh[];
    const uint32_t smem_u32 = (uint32_t)__cvta_generic_to_shared(smh);

    const int rbase = blockIdx.x * 64;
    const int tid  = threadIdx.x;
    const int lane = tid & 31;
    const int wid  = tid >> 5;
    const int g  = lane >> 2;
    const int tg = lane & 3;
    const int rp   = wid & 1;
    const int colq = wid >> 1;

    const int xrow = tid >> 2;
    const int xc16 = (tid & 3) * 16;

    float acc[2][6][4];
    #pragma unroll
    for (int mt = 0; mt < 2; mt++)
        #pragma unroll
        for (int nt = 0; nt < 6; nt++)
            #pragma unroll
            for (int e = 0; e < 4; e++) acc[mt][nt][e] = 0.f;

    #pragma unroll
    for (int i = 0; i < 6; i++) {
        int idx = tid + i * 256;
        int row = idx >> 3, c = idx & 7;
        cp16(smem_u32 + QWS * 2 + row * 144 + c * 16,
             (const char*)g_WT + (size_t)row * FDIM * 2 + c * 16);
    }
    CP_COMMIT();

    float4 xr[4];
    #pragma unroll
    for (int i = 0; i < 4; i++)
        xr[i] = *(const float4*)&x[(size_t)(rbase + xrow) * FDIM + xc16 + i * 4];

    #pragma unroll 1
    for (int kc = 0; kc < 8; kc++) {
        const int buf = kc & 1;
        __half* Xs = smh + QXS + buf * 4608;
        const __half* Ws = smh + QWS + buf * 13824;

        {
            uint4 u0, u1;
            u0.x = hpack(xr[0].x, xr[0].y); u0.y = hpack(xr[0].z, xr[0].w);
            u0.z = hpack(xr[1].x, xr[1].y); u0.w = hpack(xr[1].z, xr[1].w);
            u1.x = hpack(xr[2].x, xr[2].y); u1.y = hpack(xr[2].z, xr[2].w);
            u1.z = hpack(xr[3].x, xr[3].y); u1.w = hpack(xr[3].z, xr[3].w);
            *(uint4*)&Xs[xrow * 72 + xc16]     = u0;
            *(uint4*)&Xs[xrow * 72 + xc16 + 8] = u1;
        }
        if (kc < 7) {
            #pragma unroll
            for (int i = 0; i < 4; i++)
                xr[i] = *(const float4*)&x[(size_t)(rbase + xrow) * FDIM
                                           + (kc + 1) * 64 + xc16 + i * 4];
        }

        CP_WAIT0();
        __syncthreads();

        if (kc < 7) {
            const int nb = (kc + 1) & 1;
            #pragma unroll
            for (int i = 0; i < 6; i++) {
                int idx = tid + i * 256;
                int row = idx >> 3, c = idx & 7;
                cp16(smem_u32 + QWS * 2 + nb * 27648 + row * 144 + c * 16,
                     (const char*)g_WT + (size_t)row * FDIM * 2 + (kc + 1) * 128 + c * 16);
            }
            CP_COMMIT();
        }

        #pragma unroll
        for (int ks = 0; ks < 4; ks++) {
            const int kcol = ks * 16 + 2 * tg;
            uint32_t a[2][4];
            #pragma unroll
            for (int mt = 0; mt < 2; mt++) {
                const int r0 = rp * 32 + mt * 16;
                a[mt][0] = LDSH2(&Xs[(r0 + g    ) * 72 + kcol]);
                a[mt][1] = LDSH2(&Xs[(r0 + g + 8) * 72 + kcol]);
                a[mt][2] = LDSH2(&Xs[(r0 + g    ) * 72 + kcol + 8]);
                a[mt][3] = LDSH2(&Xs[(r0 + g + 8) * 72 + kcol + 8]);
            }
            #pragma unroll
            for (int nt = 0; nt < 6; nt++) {
                const int n = colq * 48 + nt * 8 + g;
                uint32_t b0 = LDSH2(&Ws[n * 72 + kcol]);
                uint32_t b1 = LDSH2(&Ws[n * 72 + kcol + 8]);
                mma16(acc[0][nt], a[0][0], a[0][1], a[0][2], a[0][3], b0, b1);
                mma16(acc[1][nt], a[1][0], a[1][1], a[1][2], a[1][3], b0, b1);
            }
        }
    }
    __syncthreads();

    __half* T = smh;
    #pragma unroll
    for (int mt = 0; mt < 2; mt++) {
        #pragma unroll
        for (int nt = 0; nt < 6; nt++) {
            const int n = colq * 48 + nt * 8 + 2 * tg;
            const int r0 = rbase + rp * 32 + mt * 16;
            if (n < 64) {
                *(uint32_t*)&g_Qh[(size_t)(r0 + g    ) * DDIM + n] =
                    hpack(acc[mt][nt][0], acc[mt][nt][1]);
                *(uint32_t*)&g_Qh[(size_t)(r0 + g + 8) * DDIM + n] =
                    hpack(acc[mt][nt][2], acc[mt][nt][3]);
            } else if (n < 128) {
                *(uint32_t*)&g_Kh[(size_t)(r0 + g    ) * DDIM + n - 64] =
                    hpack(acc[mt][nt][0], acc[mt][nt][1]);
                *(uint32_t*)&g_Kh[(size_t)(r0 + g + 8) * DDIM + n - 64] =
                    hpack(acc[mt][nt][2], acc[mt][nt][3]);
            } else {
                const int d = n - 128;
                const int s0 = rp * 32 + mt * 16;
                T[(d    ) * 72 + s0 + g    ] = __float2half_rn(acc[mt][nt][0]);
                T[(d + 1) * 72 + s0 + g    ] = __float2half_rn(acc[mt][nt][1]);
                T[(d    ) * 72 + s0 + g + 8] = __float2half_rn(acc[mt][nt][2]);
                T[(d + 1) * 72 + s0 + g + 8] = __float2half_rn(acc[mt][nt][3]);
            }
        }
    }
    __syncthreads();
    {
        const int b = rbase >> 12;
        const int sbase = rbase & 4095;
        #pragma unroll
        for (int i = 0; i < 2; i++) {
            int idx = tid + i * 256;
            int d = idx >> 3, c8 = idx & 7;
            uint4 v = *(const uint4*)&T[d * 72 + c8 * 8];
            *(uint4*)&g_VTh[((size_t)b * DDIM + d) * SEQ + sbase + c8 * 8] = v;
        }
    }
}

// ---------------------------------------------------------------------------
// fp16 mma flash attention: 4 warps x 32 query rows, split-K=2, 2 CTAs/SM.
// Per tile, software-pipelined by ntile-PAIR: exp(pr) and PV(pr) interleave
// with the S-MMAs of pair pr+1, so MUFU hides under HMMA issue.
// SMEM bytes: K[2][9216] V[2][9216] = 36864 B.
// ---------------------------------------------------------------------------
#define KB_OFF 0
#define VB_OFF 18432
#define SMEM_ATTN 36864

__global__ __launch_bounds__(128, 2) void attn_mma()
{
    extern __shared__ __half smah[];
    char* smb = (char*)smah;
    const uint32_t smem_u32 = (uint32_t)__cvta_generic_to_shared(smb);

    const int tid  = threadIdx.x;
    const int lane = tid & 31;
    const int wid  = tid >> 5;          // 0..3
    const int g  = lane >> 2;
    const int tg = lane & 3;
    const int b     = blockIdx.y;
    const int split = blockIdx.z;
    const int qbase = blockIdx.x * 128;
    const int qrow0 = wid * 32;

    // ---- Q fragments straight from global (fp16, pre-scaled): 32 regs ----
    const __half* Qg = g_Qh + ((size_t)b * SEQ + qbase + qrow0) * DDIM;
    uint32_t qa[2][4][4];
    #pragma unroll
    for (int mt = 0; mt < 2; mt++) {
        #pragma unroll
        for (int ks = 0; ks < 4; ks++) {
            const int kcol = ks * 16 + 2 * tg;
            qa[mt][ks][0] = *(const uint32_t*)&Qg[(size_t)(mt * 16 + g    ) * DDIM + kcol];
            qa[mt][ks][1] = *(const uint32_t*)&Qg[(size_t)(mt * 16 + g + 8) * DDIM + kcol];
            qa[mt][ks][2] = *(const uint32_t*)&Qg[(size_t)(mt * 16 + g    ) * DDIM + kcol + 8];
            qa[mt][ks][3] = *(const uint32_t*)&Qg[(size_t)(mt * 16 + g + 8) * DDIM + kcol + 8];
        }
    }

    float oacc[2][8][4];
    float lacc[2][4];
    #pragma unroll
    for (int mt = 0; mt < 2; mt++) {
        #pragma unroll
        for (int nt = 0; nt < 8; nt++)
            #pragma unroll
            for (int e = 0; e < 4; e++) oacc[mt][nt][e] = 0.f;
        #pragma unroll
        for (int e = 0; e < 4; e++) lacc[mt][e] = 0.f;
    }

    const __half* Kb = g_Kh + ((size_t)b * SEQ + (size_t)split * (SEQ / NSPLIT)) * DDIM;
    const __half* Vb = g_VTh + (size_t)b * DDIM * SEQ + (size_t)split * (SEQ / NSPLIT);

    const int frow = tid >> 1;
    const int fc   = (tid & 1) * 4;

    // prologue: tile 0 into buffer 0
    #pragma unroll
    for (int c = 0; c < 4; c++) {
        cp16(smem_u32 + KB_OFF + frow * 144 + (fc + c) * 16,
             (const char*)Kb + frow * 128 + (fc + c) * 16);
        cp16(smem_u32 + VB_OFF + frow * 144 + (fc + c) * 16,
             (const char*)Vb + (size_t)frow * (SEQ * 2) + (fc + c) * 16);
    }
    CP_COMMIT();

    #pragma unroll 1
    for (int kt = 0; kt < KT_PER; kt++) {
        // async-fill next tile (buffer released by trailing barrier of kt-1)
        {
            int nk = (kt + 1 < KT_PER) ? kt + 1 : kt;
            int nb = (kt + 1) & 1;
            const char* Kg = (const char*)(Kb + (size_t)nk * 64 * DDIM);
            const char* Vg = (const char*)(Vb + (size_t)nk * 64);
            #pragma unroll
            for (int c = 0; c < 4; c++) {
                cp16(smem_u32 + KB_OFF + nb * 9216 + frow * 144 + (fc + c) * 16,
                     Kg + frow * 128 + (fc + c) * 16);
                cp16(smem_u32 + VB_OFF + nb * 9216 + frow * 144 + (fc + c) * 16,
                     Vg + (size_t)frow * (SEQ * 2) + (fc + c) * 16);
            }
            CP_COMMIT();
        }
        CP_WAIT1();
        __syncthreads();

        const __half* Ks = (const __half*)(smb + KB_OFF) + (kt & 1) * 4608;
        const __half* Vs = (const __half*)(smb + VB_OFF) + (kt & 1) * 4608;

        // S-MMA for ntile pair pr (keys 16*pr .. 16*pr+15), both mtiles
        float sbuf[2][2][2][4];   // [pingpong][mt][nt-in-pair][4]
        auto s_pair = [&](int pr, float (*dst)[2][4]) {
            #pragma unroll
            for (int mt = 0; mt < 2; mt++)
                #pragma unroll
                for (int j = 0; j < 2; j++)
                    #pragma unroll
                    for (int e = 0; e < 4; e++) dst[mt][j][e] = 0.f;
            #pragma unroll
            for (int ks = 0; ks < 4; ks++) {
                const int kcol = ks * 16 + 2 * tg;
                #pragma unroll
                for (int j = 0; j < 2; j++) {
                    const int row = (2 * pr + j) * 8 + g;
                    uint32_t b0 = LDSH2(&Ks[row * 72 + kcol]);
                    uint32_t b1 = LDSH2(&Ks[row * 72 + kcol + 8]);
                    mma16(dst[0][j], qa[0][ks][0], qa[0][ks][1], qa[0][ks][2], qa[0][ks][3], b0, b1);
                    mma16(dst[1][j], qa[1][ks][0], qa[1][ks][1], qa[1][ks][2], qa[1][ks][3], b0, b1);
                }
            }
        };

        s_pair(0, sbuf[0]);

        #pragma unroll
        for (int pr = 0; pr < 4; pr++) {
            const int cb = pr & 1;

            // exp current pair -> PV A-fragments (independent of next s_pair)
            uint32_t p[2][4];
            #pragma unroll
            for (int mt = 0; mt < 2; mt++) {
                p[mt][0] = ex2h2(pack2(sbuf[cb][mt][0][0], sbuf[cb][mt][0][1]));
                p[mt][1] = ex2h2(pack2(sbuf[cb][mt][0][2], sbuf[cb][mt][0][3]));
                p[mt][2] = ex2h2(pack2(sbuf[cb][mt][1][0], sbuf[cb][mt][1][1]));
                p[mt][3] = ex2h2(pack2(sbuf[cb][mt][1][2], sbuf[cb][mt][1][3]));
            }

            // S-MMAs for the next pair — fills the MUFU latency window
            if (pr < 3) s_pair(pr + 1, sbuf[cb ^ 1]);

            // PV k-step pr + row-sum MMA
            const int kcol = pr * 16 + 2 * tg;
            #pragma unroll
            for (int nt = 0; nt < 8; nt++) {
                uint32_t b0 = LDSH2(&Vs[(nt * 8 + g) * 72 + kcol]);
                uint32_t b1 = LDSH2(&Vs[(nt * 8 + g) * 72 + kcol + 8]);
                mma16(oacc[0][nt], p[0][0], p[0][1], p[0][2], p[0][3], b0, b1);
                mma16(oacc[1][nt], p[1][0], p[1][1], p[1][2], p[1][3], b0, b1);
            }
            mma16(lacc[0], p[0][0], p[0][1], p[0][2], p[0][3], ONES_H2, ONES_H2);
            mma16(lacc[1], p[1][0], p[1][1], p[1][2], p[1][3], ONES_H2, ONES_H2);
        }
        __syncthreads();   // release buffer kt&1 before iter kt+1 overwrites it
    }

    // ---- store unnormalized partials (lacc identical across tg lanes) ----
    const size_t rbase = (size_t)split * M_TOTAL + (size_t)b * SEQ + qbase + qrow0;
    #pragma unroll
    for (int mt = 0; mt < 2; mt++) {
        #pragma unroll
        for (int nt = 0; nt < 8; nt++) {
            float2 o0, o1;
            o0.x = oacc[mt][nt][0]; o0.y = oacc[mt][nt][1];
            o1.x = oacc[mt][nt][2]; o1.y = oacc[mt][nt][3];
            *(float2*)&g_Opart[(rbase + mt * 16 + g    ) * DDIM + nt * 8 + 2 * tg] = o0;
            *(float2*)&g_Opart[(rbase + mt * 16 + 8 + g) * DDIM + nt * 8 + 2 * tg] = o1;
        }
    }
    if (tg == 0) {
        g_Lpart[rbase + g]          = lacc[0][0];
        g_Lpart[rbase + g + 8]      = lacc[0][2];
        g_Lpart[rbase + 16 + g]     = lacc[1][0];
        g_Lpart[rbase + 16 + g + 8] = lacc[1][2];
    }
}

// ---------------------------------------------------------------------------
// Combine: out = (O0 + O1) / (l0 + l1), 2 float4 per thread
// ---------------------------------------------------------------------------
__global__ __launch_bounds__(256) void combine(float* __restrict__ out)
{
    const int i = blockIdx.x * 256 + threadIdx.x;
    const int row = i >> 3;
    const float inv = 1.0f / (g_Lpart[row] + g_Lpart[M_TOTAL + row]);
    #pragma unroll
    for (int h = 0; h < 2; h++) {
        const size_t e = (size_t)i * 8 + h * 4;
        const float4 a = *(const float4*)&g_Opart[e];
        const float4 c = *(const float4*)&g_Opart[(size_t)M_TOTAL * DDIM + e];
        float4 r;
        r.x = (a.x + c.x) * inv;
        r.y = (a.y + c.y) * inv;
        r.z = (a.z + c.z) * inv;
        r.w = (a.w + c.w) * inv;
        *(float4*)&out[e] = r;
    }
}

// ---------------------------------------------------------------------------
extern "C" void kernel_launch(void* const* d_in, const int* in_sizes, int n_in,
                              void* d_out, int out_size)
{
    const float* x  = (const float*)d_in[0];
    const float* Wq = (const float*)d_in[1];
    const float* Wk = (const float*)d_in[2];
    const float* Wv = (const float*)d_in[3];
    float* out = (float*)d_out;

    cudaFuncSetAttribute(qkv_tc,   cudaFuncAttributeMaxDynamicSharedMemorySize, SMEM_QKV);
    cudaFuncSetAttribute(attn_mma, cudaFuncAttributeMaxDynamicSharedMemorySize, SMEM_ATTN);

    prep_w<<<192 * FDIM / 256, 256>>>(Wq, Wk, Wv);
    qkv_tc<<<M_TOTAL / 64, 256, SMEM_QKV>>>(x);
    attn_mma<<<dim3(SEQ / 128, BS, NSPLIT), 128, SMEM_ATTN>>>();
    combine<<<(M_TOTAL * DDIM / 8) / 256, 256>>>(out);
}